// round 3
// baseline (speedup 1.0000x reference)
#include <cuda_runtime.h>
#include <cuda_fp16.h>
#include <cstdint>
#include <cstring>

// ============================================================================
// ExpertsLinear: y[b,o] = sum_e weights[b,e] * (x[b,:] @ W[e])[o] + gated bias
// ONE GEMM  y = A @ B^T :
//   A[b, k] = weights[b,e] * x[b,i],  k = i*8+e          (K = 4096)
//   A[b, 4096+e] = weights[b,e]  (bias gates) ; zero pad to K_TOT = 4128
//   B[n, k] = W[e,i,n] ; B[n,4096+e] = bias[e,n] ; zero pad
// fp16 operands, fp32 accumulate via mma.sync.m16n8k16 (portable HMMA —
// tcgen05 is rejected by this toolchain's .target sm_103).
// ============================================================================

#define EXPERTS   8
#define IN_DIM    512
#define OUT_DIM   512
#define BATCH     65536
#define K_GEMM    4096
#define K_TOT     4128          // 129 chunks of 32
#define NCH       129
#define M_TILE    256
#define N_TILE    128
#define NTHREADS  256

#define A_TILE_BYTES  (M_TILE * 64)    // 256 rows x 32 half = 16 KB
#define B_TILE_BYTES  (N_TILE * 64)    // 128 rows x 32 half = 8 KB
#define STAGE_BYTES   (A_TILE_BYTES + B_TILE_BYTES)   // 24 KB
#define SMEM_BYTES    (2 * STAGE_BYTES)               // 48 KB

// Permuted fp16 B built by prepass: g_Bt[n * K_TOT + k]
__device__ __align__(16) __half g_Bt[(size_t)OUT_DIM * K_TOT];

// ---------------------------------------------------------------------------
// helpers
// ---------------------------------------------------------------------------
__device__ __forceinline__ uint32_t smem_u32(const void* p) {
    uint32_t a;
    asm("{ .reg .u64 t; cvta.to.shared.u64 t, %1; cvt.u32.u64 %0, t; }"
        : "=r"(a) : "l"(p));
    return a;
}
// XOR swizzle for 64B-row tiles: conflict-free for ldmatrix + STS.128
__device__ __forceinline__ uint32_t swz(uint32_t b) {
    return b ^ ((b >> 3) & 0x30);
}
__device__ __forceinline__ uint32_t pack_h2(float a, float b) {
    __half2 h = __floats2half2_rn(a, b);
    uint32_t u; memcpy(&u, &h, 4); return u;
}

#define CP_ASYNC16(dst, src) \
    asm volatile("cp.async.cg.shared.global [%0], [%1], 16;" \
        :: "r"(dst), "l"(src) : "memory")
#define CP_COMMIT() asm volatile("cp.async.commit_group;" ::: "memory")
#define CP_WAIT0()  asm volatile("cp.async.wait_group 0;" ::: "memory")

#define LDSM_X4(r0, r1, r2, r3, addr) \
    asm volatile("ldmatrix.sync.aligned.m8n8.x4.shared.b16 {%0,%1,%2,%3}, [%4];" \
        : "=r"(r0), "=r"(r1), "=r"(r2), "=r"(r3) : "r"(addr))

#define STS128(addr, r0, r1, r2, r3) \
    asm volatile("st.shared.v4.b32 [%0], {%1,%2,%3,%4};" \
        :: "r"(addr), "r"(r0), "r"(r1), "r"(r2), "r"(r3) : "memory")

#define MMA16816(d, a, b) \
    asm volatile("mma.sync.aligned.m16n8k16.row.col.f32.f16.f16.f32 " \
        "{%0,%1,%2,%3}, {%4,%5,%6,%7}, {%8,%9}, {%0,%1,%2,%3};" \
        : "+f"((d)[0]), "+f"((d)[1]), "+f"((d)[2]), "+f"((d)[3]) \
        : "r"((a)[0]), "r"((a)[1]), "r"((a)[2]), "r"((a)[3]), \
          "r"((b)[0]), "r"((b)[1]))

// ---------------------------------------------------------------------------
// Prepass: build permuted fp16 B (+bias rows, zero pad)
// ---------------------------------------------------------------------------
__global__ void prep_b_kernel(const float* __restrict__ W,
                              const float* __restrict__ bias) {
    int idx = blockIdx.x * 256 + threadIdx.x;
    if (idx >= OUT_DIM * K_TOT) return;
    int n = idx / K_TOT;
    int k = idx - n * K_TOT;
    float v = 0.0f;
    if (k < K_GEMM) {
        int i = k >> 3, e = k & 7;
        v = W[((size_t)e * IN_DIM + i) * OUT_DIM + n];
    } else if (k < K_GEMM + EXPERTS) {
        v = bias[(size_t)(k - K_GEMM) * OUT_DIM + n];
    }
    g_Bt[idx] = __float2half_rn(v);
}

// ---------------------------------------------------------------------------
// Main GEMM
// ---------------------------------------------------------------------------
__global__ void __launch_bounds__(NTHREADS, 1)
moe_gemm_kernel(const float* __restrict__ x,
                const float* __restrict__ wts,
                float* __restrict__ out) {
    extern __shared__ char smem[];
    const uint32_t sbase = smem_u32(smem);

    const int tid  = threadIdx.x;
    const int wid  = tid >> 5;
    const int lane = tid & 31;
    const int wm   = wid & 3;            // warp m index (4 x 64 rows)
    const int wn   = wid >> 2;           // warp n index (2 x 64 cols)

    const int b0 = blockIdx.y * M_TILE;
    const int o0 = blockIdx.x * N_TILE;

    // ---- gates for this thread's A row ----
    const float4* w4 = reinterpret_cast<const float4*>(wts + (size_t)(b0 + tid) * EXPERTS);
    const float4 wa = w4[0], wb = w4[1];
    const float wreg[8] = {wa.x, wa.y, wa.z, wa.w, wb.x, wb.y, wb.z, wb.w};
    const uint32_t gh0 = pack_h2(wreg[0], wreg[1]);
    const uint32_t gh1 = pack_h2(wreg[2], wreg[3]);
    const uint32_t gh2 = pack_h2(wreg[4], wreg[5]);
    const uint32_t gh3 = pack_h2(wreg[6], wreg[7]);

    const float4* xrow = reinterpret_cast<const float4*>(x + (size_t)(b0 + tid) * IN_DIM);

    // ---- A build destinations (swizzled, per-stage offset added later) ----
    uint32_t a_sw[4];
    #pragma unroll
    for (int g = 0; g < 4; g++) a_sw[g] = swz((uint32_t)tid * 64 + g * 16);

    // ---- B cp.async: thread handles granules G=tid and G=tid+256 of 512 ----
    const int brow0 = tid >> 2;          // 0..63
    const int bg    = tid & 3;
    const uint32_t b_sw0 = A_TILE_BYTES + swz((uint32_t)brow0 * 64 + bg * 16);
    const uint32_t b_sw1 = A_TILE_BYTES + swz((uint32_t)(brow0 + 64) * 64 + bg * 16);
    const char* bsrc0 = reinterpret_cast<const char*>(
        g_Bt + (size_t)(o0 + brow0) * K_TOT + bg * 8);
    const char* bsrc1 = reinterpret_cast<const char*>(
        g_Bt + (size_t)(o0 + brow0 + 64) * K_TOT + bg * 8);

    // ---- ldmatrix row bases ----
    uint32_t a_ldrow[4], b_ldrow[4];
    #pragma unroll
    for (int mt = 0; mt < 4; mt++)
        a_ldrow[mt] = (uint32_t)(wm * 64 + mt * 16 + (lane & 15)) * 64;
    #pragma unroll
    for (int bt = 0; bt < 4; bt++)
        b_ldrow[bt] = (uint32_t)(wn * 64 + bt * 16 + ((lane >> 4) << 3) + (lane & 7)) * 64;
    const uint32_t a_kg = (uint32_t)(lane >> 4) * 16;        // 0 or 16
    const uint32_t b_kg = (uint32_t)((lane >> 3) & 1) * 16;  // 0 or 16

    float acc[4][8][4];
    #pragma unroll
    for (int mt = 0; mt < 4; mt++)
        #pragma unroll
        for (int nt = 0; nt < 8; nt++)
            #pragma unroll
            for (int i = 0; i < 4; i++) acc[mt][nt][i] = 0.0f;

    // ================= prologue: fill stage 0 with chunk 0 =================
    float4 xc = xrow[0];
    {
        const uint32_t ab = sbase;  // stage 0
        const float xs[4] = {xc.x, xc.y, xc.z, xc.w};
        #pragma unroll
        for (int g = 0; g < 4; g++) {
            const float xv = xs[g];
            STS128(ab + a_sw[g],
                   pack_h2(xv * wreg[0], xv * wreg[1]),
                   pack_h2(xv * wreg[2], xv * wreg[3]),
                   pack_h2(xv * wreg[4], xv * wreg[5]),
                   pack_h2(xv * wreg[6], xv * wreg[7]));
        }
        CP_ASYNC16(sbase + b_sw0, bsrc0);
        CP_ASYNC16(sbase + b_sw1, bsrc1);
        CP_COMMIT();
    }
    float4 xn = xrow[1];

    // ================= main loop =================
    uint32_t st = 0;
    for (int c = 0; c < NCH; c++) {
        CP_WAIT0();
        __syncthreads();

        const uint32_t cur_base = sbase + st * STAGE_BYTES;
        const uint32_t nst = st ^ 1;

        if (c + 1 < NCH) {
            const uint32_t nb = sbase + nst * STAGE_BYTES;
            // B tile chunk c+1
            CP_ASYNC16(nb + b_sw0, bsrc0 + (size_t)(c + 1) * 64);
            CP_ASYNC16(nb + b_sw1, bsrc1 + (size_t)(c + 1) * 64);
            CP_COMMIT();
            // A tile chunk c+1
            if (c + 1 < 128) {
                const float xs[4] = {xn.x, xn.y, xn.z, xn.w};
                #pragma unroll
                for (int g = 0; g < 4; g++) {
                    const float xv = xs[g];
                    STS128(nb + a_sw[g],
                           pack_h2(xv * wreg[0], xv * wreg[1]),
                           pack_h2(xv * wreg[2], xv * wreg[3]),
                           pack_h2(xv * wreg[4], xv * wreg[5]),
                           pack_h2(xv * wreg[6], xv * wreg[7]));
                }
                if (c + 2 < 128) xn = xrow[c + 2];
            } else {
                // tail chunk: k=4096+e carries the gate, rest zero
                STS128(nb + a_sw[0], gh0, gh1, gh2, gh3);
                STS128(nb + a_sw[1], 0u, 0u, 0u, 0u);
                STS128(nb + a_sw[2], 0u, 0u, 0u, 0u);
                STS128(nb + a_sw[3], 0u, 0u, 0u, 0u);
            }
        }

        // ---- MMA on current stage ----
        const uint32_t a_base = cur_base;
        const uint32_t b_base = cur_base + A_TILE_BYTES;
        #pragma unroll
        for (int s = 0; s < 2; s++) {
            uint32_t af[4][4], bf[8][2];
            #pragma unroll
            for (int mt = 0; mt < 4; mt++) {
                const uint32_t addr = a_base + swz(a_ldrow[mt] + s * 32 + a_kg);
                LDSM_X4(af[mt][0], af[mt][1], af[mt][2], af[mt][3], addr);
            }
            #pragma unroll
            for (int bt = 0; bt < 4; bt++) {
                const uint32_t addr = b_base + swz(b_ldrow[bt] + s * 32 + b_kg);
                LDSM_X4(bf[2 * bt][0], bf[2 * bt][1],
                        bf[2 * bt + 1][0], bf[2 * bt + 1][1], addr);
            }
            #pragma unroll
            for (int mt = 0; mt < 4; mt++)
                #pragma unroll
                for (int nt = 0; nt < 8; nt++)
                    MMA16816(acc[mt][nt], af[mt], bf[nt]);
        }
        st = nst;
    }

    // ================= epilogue: direct coalesced stores =================
    const int r0 = (lane >> 2);          // 0..7
    const int cc = (lane & 3) * 2;
    #pragma unroll
    for (int mt = 0; mt < 4; mt++) {
        const int grow = b0 + wm * 64 + mt * 16 + r0;
        float* orow0 = out + (size_t)grow * OUT_DIM + o0 + wn * 64 + cc;
        float* orow1 = orow0 + 8 * OUT_DIM;
        #pragma unroll
        for (int nt = 0; nt < 8; nt++) {
            float2 v0 = make_float2(acc[mt][nt][0], acc[mt][nt][1]);
            float2 v1 = make_float2(acc[mt][nt][2], acc[mt][nt][3]);
            *reinterpret_cast<float2*>(orow0 + nt * 8) = v0;
            *reinterpret_cast<float2*>(orow1 + nt * 8) = v1;
        }
    }
}

// ---------------------------------------------------------------------------
// Launch
// ---------------------------------------------------------------------------
extern "C" void kernel_launch(void* const* d_in, const int* in_sizes, int n_in,
                              void* d_out, int out_size) {
    const float* x   = (const float*)d_in[0];   // [65536, 512]
    const float* wts = (const float*)d_in[1];   // [65536, 8]
    const float* W   = (const float*)d_in[2];   // [8, 512, 512]
    const float* b   = (const float*)d_in[3];   // [8, 1, 512]
    float* out = (float*)d_out;                 // [65536, 512]

    prep_b_kernel<<<(OUT_DIM * K_TOT + 255) / 256, 256>>>(W, b);

    cudaFuncSetAttribute(moe_gemm_kernel,
                         cudaFuncAttributeMaxDynamicSharedMemorySize,
                         SMEM_BYTES);
    dim3 grid(OUT_DIM / N_TILE, BATCH / M_TILE);   // (4, 256)
    moe_gemm_kernel<<<grid, NTHREADS, SMEM_BYTES>>>(x, wts, out);
}